// round 16
// baseline (speedup 1.0000x reference)
#include <cuda_runtime.h>
#include <cuda_bf16.h>
#include <cstdint>

#define CCH 64
#define CO 8
#define WIN 13
#define WPB 8
#define TP 104
#define TILES_PER_CTA 2
#define NVOX 53248
#define TILES_PER_B 512
#define CTAS_PER_B (TILES_PER_B / TILES_PER_CTA)   // 256
#define NTHREADS 256

#define APB 272          // A row pitch bytes: [hi 128B | lo 128B + pad]
#define BPB 112          // B row pitch bytes
#define ZSP 108          // z pitch words
#define QKP 12           // qT/kT row pitch words
#define ARP 16           // att row pitch words
#define AWS 212          // att window stride words: distinct banks across pt
#define OBP 108          // staged out pitch

#define A_BYTES (80 * APB)   // 21760

// smem byte offsets (total 74048 -> 3 CTAs/SM)
#define OFF_A    0       // 80*272 = 21760
#define OFF_BH   21760   // 64*112 = 7168
#define OFF_BL   28928   // 7168 -> 36096 (GEMM region; dead after mainloop)
#define OFF_OBUF 0       // 27648 (aliases A -- A re-copied per tile? NO: see note)
#define OFF_ATT  27648   // 8*212*4 = 6784 -> 34432 (aliases BH tail/BL; used post-GEMM)
#define OFF_Z    36096   // 64*108*4 = 27648 -> 63744
#define OFF_QT   63744   // 104*12*4 = 4992
#define OFF_KT   68736   // 4992 -> 73728
#define OFF_BQ   73728
#define OFF_BK   73760
#define OFF_BV   73792   // 256 -> 74048
#define SMEM_BYTES 74048

// NOTE on aliasing: obuf aliases A, so A must be re-copied at the start of each
// tile iteration. The copy is cheap (L2-hot) and still amortizes the *global*
// prologue (biases, launch overhead); more importantly the obuf region cannot
// go anywhere else without blowing the 3-CTA smem budget. A-copy per tile is
// ~170 wf, vs ~340 wf saved on launch-side prologue per extra tile -- net win
// comes from launch/drain amortization and bias/index setup.

typedef unsigned long long u64;

__device__ uint4 g_Abuf[A_BYTES / 16];

__device__ __forceinline__ u64 fma2(u64 a, u64 b, u64 c) {
    u64 d; asm("fma.rn.f32x2 %0, %1, %2, %3;" : "=l"(d) : "l"(a), "l"(b), "l"(c));
    return d;
}
__device__ __forceinline__ u64 mul2(u64 a, u64 b) {
    u64 d; asm("mul.rn.f32x2 %0, %1, %2;" : "=l"(d) : "l"(a), "l"(b));
    return d;
}
__device__ __forceinline__ u64 pack2(float lo, float hi) {
    u64 d; asm("mov.b64 %0, {%1, %2};" : "=l"(d) : "f"(lo), "f"(hi));
    return d;
}
__device__ __forceinline__ float lo2(u64 v) { return __uint_as_float((unsigned)v); }
__device__ __forceinline__ float hi2(u64 v) { return __uint_as_float((unsigned)(v >> 32)); }

__device__ __forceinline__ uint32_t smem_u32(const void* p) {
    uint32_t a;
    asm("{ .reg .u64 t; cvta.to.shared.u64 t, %1; cvt.u32.u64 %0, t; }" : "=r"(a) : "l"(p));
    return a;
}
__device__ __forceinline__ void ldsm4(uint32_t* r, uint32_t addr) {
    asm volatile("ldmatrix.sync.aligned.m8n8.x4.shared.b16 {%0,%1,%2,%3}, [%4];"
                 : "=r"(r[0]), "=r"(r[1]), "=r"(r[2]), "=r"(r[3]) : "r"(addr));
}
__device__ __forceinline__ void ldsm4t(uint32_t* r, uint32_t addr) {
    asm volatile("ldmatrix.sync.aligned.m8n8.x4.trans.shared.b16 {%0,%1,%2,%3}, [%4];"
                 : "=r"(r[0]), "=r"(r[1]), "=r"(r[2]), "=r"(r[3]) : "r"(addr));
}
__device__ __forceinline__ void mma16816(float* d, const uint32_t* a, const uint32_t* b) {
    asm volatile(
        "mma.sync.aligned.m16n8k16.row.col.f32.bf16.bf16.f32 "
        "{%0,%1,%2,%3}, {%4,%5,%6,%7}, {%8,%9}, {%0,%1,%2,%3};"
        : "+f"(d[0]), "+f"(d[1]), "+f"(d[2]), "+f"(d[3])
        : "r"(a[0]), "r"(a[1]), "r"(a[2]), "r"(a[3]), "r"(b[0]), "r"(b[1]));
}

__device__ __forceinline__ void split_pack_fast(float4 v, uint2& hp, uint2& lp) {
    uint32_t h01, h23;
    asm("cvt.rn.bf16x2.f32 %0, %1, %2;" : "=r"(h01) : "f"(v.y), "f"(v.x));
    asm("cvt.rn.bf16x2.f32 %0, %1, %2;" : "=r"(h23) : "f"(v.w), "f"(v.z));
    float h0 = __uint_as_float(h01 << 16);
    float h1 = __uint_as_float(h01 & 0xFFFF0000u);
    float h2 = __uint_as_float(h23 << 16);
    float h3 = __uint_as_float(h23 & 0xFFFF0000u);
    uint32_t l01, l23;
    asm("cvt.rn.bf16x2.f32 %0, %1, %2;" : "=r"(l01) : "f"(v.y - h1), "f"(v.x - h0));
    asm("cvt.rn.bf16x2.f32 %0, %1, %2;" : "=r"(l23) : "f"(v.w - h3), "f"(v.z - h2));
    hp.x = h01; hp.y = h23;
    lp.x = l01; lp.y = l23;
}

// ---- prepass: 20 CTAs x 128 thr, 4 rows each -> bf16 hi|lo smem image ----
__global__ void prep_A_kernel(const float* __restrict__ wq,
                              const float* __restrict__ wk,
                              const float* __restrict__ wv) {
    char* dst = (char*)g_Abuf;
    int f = blockIdx.x * 64 + (threadIdx.x & 63);   // 20*64 = 1280 items
    if ((threadIdx.x & 64) == 0) {
        int row = f >> 4, c4 = f & 15;
        const float* src = (row < 64) ? (wv + row * 64 + c4 * 4)
                         : (row < 72) ? (wq + (row - 64) * 64 + c4 * 4)
                                      : (wk + (row - 72) * 64 + c4 * 4);
        float4 v = *(const float4*)src;
        uint2 hp, lp;
        split_pack_fast(v, hp, lp);
        *(uint2*)(dst + row * APB + c4 * 8) = hp;
        *(uint2*)(dst + row * APB + 128 + c4 * 8) = lp;
    }
}

template<int NT>
__device__ __forceinline__ void gemm_unit(
    const uint32_t sb, char* smem, int h, int m, int ntBeg, int lid)
{
    float* s_z  = (float*)(smem + OFF_Z);
    float* s_qT = (float*)(smem + OFF_QT);
    float* s_kT = (float*)(smem + OFF_KT);
    float* s_bq = (float*)(smem + OFF_BQ);
    float* s_bk = (float*)(smem + OFF_BK);

    float d[NT * 4];
#pragma unroll
    for (int i = 0; i < NT * 4; i++) d[i] = 0.f;

    const uint32_t aaddr = sb + OFF_A + (uint32_t)(lid & 15) * APB
                         + (uint32_t)(lid & 16) + (uint32_t)(16 * m) * APB;

#pragma unroll
    for (int ktp = 0; ktp < 2; ktp++) {
        uint32_t ah[8], al[8];
        ldsm4(ah,     aaddr + ktp * 64);
        ldsm4(ah + 4, aaddr + ktp * 64 + 32);
        ldsm4(al,     aaddr + 128 + ktp * 64);
        ldsm4(al + 4, aaddr + 128 + ktp * 64 + 32);
        uint32_t brow = sb + (uint32_t)(ktp * 32 + lid) * BPB;
#pragma unroll
        for (int j = 0; j < NT; j++) {
            int nt = ntBeg + j;
            uint32_t bh[4], bl[4];
            ldsm4t(bh, brow + OFF_BH + nt * 16);
            ldsm4t(bl, brow + OFF_BL + nt * 16);
            float* dj = d + 4 * j;
            mma16816(dj, ah,     bh);
            mma16816(dj, ah,     bl);
            mma16816(dj, al,     bh);
            mma16816(dj, ah + 4, bh + 2);
            mma16816(dj, ah + 4, bl + 2);
            mma16816(dj, al + 4, bh + 2);
        }
    }

    int r = lid >> 2;
#pragma unroll
    for (int j = 0; j < NT; j++) {
        int nt = ntBeg + j;
        int gp = h * 48 + nt * 8 + 2 * (lid & 3);
        float* dj = d + 4 * j;
        if (m < 4) {
            *(float2*)(s_z + (16 * m + r) * ZSP + gp)     = make_float2(dj[0], dj[1]);
            *(float2*)(s_z + (16 * m + r + 8) * ZSP + gp) = make_float2(dj[2], dj[3]);
        } else {
            float bqv = s_bq[r], bkv = s_bk[r];
            s_qT[gp * QKP + r]       = dj[0] + bqv;
            s_qT[(gp + 1) * QKP + r] = dj[1] + bqv;
            s_kT[gp * QKP + r]       = dj[2] + bkv;
            s_kT[(gp + 1) * QKP + r] = dj[3] + bkv;
        }
    }
}

__global__ __launch_bounds__(NTHREADS, 3)
void win_attn_kernel(const float* __restrict__ x,
                     const float* __restrict__ wq, const float* __restrict__ bq,
                     const float* __restrict__ wk, const float* __restrict__ bk,
                     const float* __restrict__ wv, const float* __restrict__ bv,
                     float* __restrict__ out) {
    extern __shared__ char smem[];
    const uint32_t sb = smem_u32(smem);
    float* s_z   = (float*)(smem + OFF_Z);
    float* s_qT  = (float*)(smem + OFF_QT);
    float* s_kT  = (float*)(smem + OFF_KT);
    float* s_att = (float*)(smem + OFF_ATT);
    float* s_bq  = (float*)(smem + OFF_BQ);
    float* s_bk  = (float*)(smem + OFF_BK);
    float* s_bv  = (float*)(smem + OFF_BV);
    float* obuf  = (float*)(smem + OFF_OBUF);

    const int tid = threadIdx.x;
    const int wid = tid >> 5;
    const int lid = tid & 31;

    const int b     = blockIdx.x / CTAS_PER_B;
    const int ctile = blockIdx.x % CTAS_PER_B;

    // ---- biases (once per CTA) ----
    if (tid < CO)                      s_bq[tid]       = bq[tid];
    if (tid >= 64 && tid < 64 + CO)    s_bk[tid - 64]  = bk[tid - 64];
    if (tid >= 128 && tid < 128 + CCH) s_bv[tid - 128] = bv[tid - 128];

    const int mA = wid >> 1;
    const int ng = wid & 1;

    for (int tt = 0; tt < TILES_PER_CTA; tt++) {
        const int tile = ctile * TILES_PER_CTA + tt;
        const long n0  = (long)tile * TP;
        const float* xb = x   + (long)b * CCH * NVOX + n0;
        float*       ob = out + (long)b * CCH * NVOX + n0;

        // ---- A: copy pre-converted image (L2-hot; re-copied since obuf aliases) ----
        {
            uint4* dsta = (uint4*)(smem + OFF_A);
            for (int f = tid; f < A_BYTES / 16; f += NTHREADS)
                dsta[f] = g_Abuf[f];
        }
        // ---- B half 0 ----
        for (int f = tid; f < CCH * 14; f += NTHREADS) {
            int ch = f / 14, p4 = f % 14;
            float4 v = *(const float4*)(xb + (long)ch * NVOX + p4 * 4);
            uint2 hp, lp;
            split_pack_fast(v, hp, lp);
            *(uint2*)(smem + OFF_BH + ch * BPB + p4 * 8) = hp;
            *(uint2*)(smem + OFF_BL + ch * BPB + p4 * 8) = lp;
        }
        __syncthreads();

        // ---- GEMM: two 56-pos halves ----
        for (int h = 0; h < 2; h++) {
            if (h == 1) {
                __syncthreads();
                for (int f = tid; f < CCH * 14; f += NTHREADS) {
                    int ch = f / 14, p4 = f % 14;
                    float4 v = *(const float4*)(xb + (long)ch * NVOX + 48 + p4 * 4);
                    uint2 hp, lp;
                    split_pack_fast(v, hp, lp);
                    *(uint2*)(smem + OFF_BH + ch * BPB + p4 * 8) = hp;
                    *(uint2*)(smem + OFF_BL + ch * BPB + p4 * 8) = lp;
                }
                __syncthreads();
            }
            if (wid == 0) {
                gemm_unit<4>(sb, smem, h, 0, 0, lid);
                gemm_unit<4>(sb, smem, h, 4, 0, lid);
            } else if (wid == 1) {
                gemm_unit<3>(sb, smem, h, 0, 4, lid);
                gemm_unit<3>(sb, smem, h, 4, 4, lid);
            } else if (ng == 0) {
                gemm_unit<4>(sb, smem, h, mA, 0, lid);
            } else {
                gemm_unit<3>(sb, smem, h, mA, 4, lid);
            }
        }
        __syncthreads();

        // ---- scores ----
        for (int m = tid; m < WPB * WIN * WIN; m += NTHREADS) {
            int w  = m / (WIN * WIN);
            int ij = m % (WIN * WIN);
            int ii = ij / WIN, jj = ij % WIN;
            ulonglong2 qa = *(const ulonglong2*)&s_qT[(w * WIN + ii) * QKP];
            ulonglong2 qb = *(const ulonglong2*)&s_qT[(w * WIN + ii) * QKP + 4];
            ulonglong2 ka = *(const ulonglong2*)&s_kT[(w * WIN + jj) * QKP];
            ulonglong2 kb = *(const ulonglong2*)&s_kT[(w * WIN + jj) * QKP + 4];
            u64 acc = fma2(qa.x, ka.x,
                      fma2(qa.y, ka.y,
                      fma2(qb.x, kb.x,
                      mul2(qb.y, kb.y))));
            s_att[w * AWS + ii * ARP + jj] = lo2(acc) + hi2(acc);
        }
        __syncthreads();

        // ---- softmax ----
        if (tid < TP) {
            int w = tid / WIN, ii = tid % WIN;
            float* row = &s_att[w * AWS + ii * ARP];
            float4 ra = *(const float4*)row;
            float4 rb = *(const float4*)(row + 4);
            float4 rc = *(const float4*)(row + 8);
            float  rd = row[12];
            float m0 = fmaxf(fmaxf(fmaxf(ra.x, ra.y), fmaxf(ra.z, ra.w)),
                       fmaxf(fmaxf(fmaxf(rb.x, rb.y), fmaxf(rb.z, rb.w)),
                       fmaxf(fmaxf(fmaxf(rc.x, rc.y), fmaxf(rc.z, rc.w)), rd)));
            ra.x = __expf(ra.x - m0); ra.y = __expf(ra.y - m0);
            ra.z = __expf(ra.z - m0); ra.w = __expf(ra.w - m0);
            rb.x = __expf(rb.x - m0); rb.y = __expf(rb.y - m0);
            rb.z = __expf(rb.z - m0); rb.w = __expf(rb.w - m0);
            rc.x = __expf(rc.x - m0); rc.y = __expf(rc.y - m0);
            rc.z = __expf(rc.z - m0); rc.w = __expf(rc.w - m0);
            rd   = __expf(rd   - m0);
            float sum = ra.x + ra.y + ra.z + ra.w + rb.x + rb.y + rb.z + rb.w
                      + rc.x + rc.y + rc.z + rc.w + rd;
            float inv = __frcp_rn(sum);
            ra.x *= inv; ra.y *= inv; ra.z *= inv; ra.w *= inv;
            rb.x *= inv; rb.y *= inv; rb.z *= inv; rb.w *= inv;
            rc.x *= inv; rc.y *= inv; rc.z *= inv; rc.w *= inv;
            rd   *= inv;
            *(float4*)row       = ra;
            *(float4*)(row + 4) = rb;
            *(float4*)(row + 8) = rc;
            row[12] = rd;
        }
        __syncthreads();

        // ---- att-apply -> staged obuf ----
        {
            const int ct = tid >> 3;
            const int pt = tid & 7;
            const int c0 = ct * 2;

            const float* zr0 = s_z + c0 * ZSP + pt * WIN;
            const float* zr1 = zr0 + ZSP;
            float z0[WIN], z1[WIN];
#pragma unroll
            for (int j = 0; j < WIN; j++) { z0[j] = zr0[j]; z1[j] = zr1[j]; }

            u64 zp0[6], zp1[6];
#pragma unroll
            for (int q = 0; q < 6; q++) {
                zp0[q] = pack2(z0[2*q], z0[2*q + 1]);
                zp1[q] = pack2(z1[2*q], z1[2*q + 1]);
            }
            const float z0s = z0[12], z1s = z1[12];

            const float* ar = &s_att[pt * AWS];
            const float bv0 = s_bv[c0], bv1 = s_bv[c0 + 1];
            float* ob0 = obuf + c0 * OBP + pt * WIN;
            float* ob1 = ob0 + OBP;
#pragma unroll
            for (int i = 0; i < WIN; i++) {
                const float* ari = ar + i * ARP;
                ulonglong2 aA = *(const ulonglong2*)ari;
                ulonglong2 aB = *(const ulonglong2*)(ari + 4);
                ulonglong2 aC = *(const ulonglong2*)(ari + 8);
                float a12 = ari[12];
                u64 s0 = fma2(zp0[0], aA.x,
                         fma2(zp0[1], aA.y,
                         fma2(zp0[2], aB.x,
                         fma2(zp0[3], aB.y,
                         fma2(zp0[4], aC.x,
                         mul2(zp0[5], aC.y))))));
                u64 s1 = fma2(zp1[0], aA.x,
                         fma2(zp1[1], aA.y,
                         fma2(zp1[2], aB.x,
                         fma2(zp1[3], aB.y,
                         fma2(zp1[4], aC.x,
                         mul2(zp1[5], aC.y))))));
                ob0[i] = lo2(s0) + hi2(s0) + fmaf(z0s, a12, bv0);
                ob1[i] = lo2(s1) + hi2(s1) + fmaf(z1s, a12, bv1);
            }
        }
        __syncthreads();

        // ---- coalesced global store ----
        for (int i = tid; i < CCH * (TP / 4); i += NTHREADS) {
            int r  = i / (TP / 4);
            int c4 = i % (TP / 4);
            float4 v = *reinterpret_cast<const float4*>(obuf + r * OBP + c4 * 4);
            *reinterpret_cast<float4*>(ob + (long)r * NVOX + c4 * 4) = v;
        }
        __syncthreads();   // obuf (aliasing A) must drain before next tile's A copy
    }
}

extern "C" void kernel_launch(void* const* d_in, const int* in_sizes, int n_in,
                              void* d_out, int out_size) {
    const float* x  = (const float*)d_in[0];
    const float* wq = (const float*)d_in[1];
    const float* bq = (const float*)d_in[2];
    const float* wk = (const float*)d_in[3];
    const float* bk = (const float*)d_in[4];
    const float* wv = (const float*)d_in[5];
    const float* bv = (const float*)d_in[6];
    float* out = (float*)d_out;

    const int B = in_sizes[0] / (CCH * NVOX);   // 8

    static bool attr_set = false;
    if (!attr_set) {
        cudaFuncSetAttribute(win_attn_kernel,
                             cudaFuncAttributeMaxDynamicSharedMemorySize, SMEM_BYTES);
        attr_set = true;
    }

    prep_A_kernel<<<20, 128>>>(wq, wk, wv);
    dim3 grid(B * CTAS_PER_B);
    win_attn_kernel<<<grid, NTHREADS, SMEM_BYTES>>>(x, wq, bq, wk, bk, wv, bv, out);
}

// round 17
// speedup vs baseline: 1.0724x; 1.0724x over previous
#include <cuda_runtime.h>
#include <cuda_bf16.h>
#include <cstdint>

#define CCH 64
#define CO 8
#define WIN 13
#define WPB 8
#define TP 104
#define NVOX 53248
#define TILES_PER_B 512
#define NTHREADS 256

#define APB 272          // A row pitch bytes: [hi 128B | lo 128B + pad]
#define BPB 112          // B row pitch bytes
#define ZSP 108          // z pitch words
#define QKP 12           // qT/kT row pitch words
#define ARP 16           // att row pitch words
#define AWS 212          // att window stride words: distinct banks across pt
#define OBP 108          // staged out pitch

#define A_BYTES (80 * APB)   // 21760

// smem byte offsets (total 74048 -> 3 CTAs/SM)
#define OFF_A    0       // 80*272 = 21760
#define OFF_BH   21760   // 64*112 = 7168
#define OFF_BL   28928   // 7168 -> 36096 (GEMM region; dead after mainloop)
#define OFF_OBUF 0       // 27648 (aliases A)
#define OFF_ATT  27648   // 8*212*4 = 6784 -> 34432 (aliases BH tail/BL; used post-GEMM)
#define OFF_Z    36096   // 64*108*4 = 27648 -> 63744
#define OFF_QT   63744   // 104*12*4 = 4992
#define OFF_KT   68736   // 4992 -> 73728
#define OFF_BQ   73728
#define OFF_BK   73760
#define OFF_BV   73792   // 256 -> 74048
#define SMEM_BYTES 74048

typedef unsigned long long u64;

// Pre-converted A tile (bf16 hi/lo, exact smem image), produced by prep_A.
__device__ uint4 g_Abuf[A_BYTES / 16];

__device__ __forceinline__ u64 fma2(u64 a, u64 b, u64 c) {
    u64 d; asm("fma.rn.f32x2 %0, %1, %2, %3;" : "=l"(d) : "l"(a), "l"(b), "l"(c));
    return d;
}
__device__ __forceinline__ u64 mul2(u64 a, u64 b) {
    u64 d; asm("mul.rn.f32x2 %0, %1, %2;" : "=l"(d) : "l"(a), "l"(b));
    return d;
}
__device__ __forceinline__ u64 pack2(float lo, float hi) {
    u64 d; asm("mov.b64 %0, {%1, %2};" : "=l"(d) : "f"(lo), "f"(hi));
    return d;
}
__device__ __forceinline__ float lo2(u64 v) { return __uint_as_float((unsigned)v); }
__device__ __forceinline__ float hi2(u64 v) { return __uint_as_float((unsigned)(v >> 32)); }

__device__ __forceinline__ uint32_t smem_u32(const void* p) {
    uint32_t a;
    asm("{ .reg .u64 t; cvta.to.shared.u64 t, %1; cvt.u32.u64 %0, t; }" : "=r"(a) : "l"(p));
    return a;
}
__device__ __forceinline__ void ldsm4(uint32_t* r, uint32_t addr) {
    asm volatile("ldmatrix.sync.aligned.m8n8.x4.shared.b16 {%0,%1,%2,%3}, [%4];"
                 : "=r"(r[0]), "=r"(r[1]), "=r"(r[2]), "=r"(r[3]) : "r"(addr));
}
__device__ __forceinline__ void ldsm4t(uint32_t* r, uint32_t addr) {
    asm volatile("ldmatrix.sync.aligned.m8n8.x4.trans.shared.b16 {%0,%1,%2,%3}, [%4];"
                 : "=r"(r[0]), "=r"(r[1]), "=r"(r[2]), "=r"(r[3]) : "r"(addr));
}
__device__ __forceinline__ void mma16816(float* d, const uint32_t* a, const uint32_t* b) {
    asm volatile(
        "mma.sync.aligned.m16n8k16.row.col.f32.bf16.bf16.f32 "
        "{%0,%1,%2,%3}, {%4,%5,%6,%7}, {%8,%9}, {%0,%1,%2,%3};"
        : "+f"(d[0]), "+f"(d[1]), "+f"(d[2]), "+f"(d[3])
        : "r"(a[0]), "r"(a[1]), "r"(a[2]), "r"(a[3]), "r"(b[0]), "r"(b[1]));
}

// Fast hi/lo bf16 split: cvt.rn.bf16x2 packs 2 floats/instr; hi recovered by
// shift/mask. Rounding identical to __float2bfloat16 (rn).
__device__ __forceinline__ void split_pack_fast(float4 v, uint2& hp, uint2& lp) {
    uint32_t h01, h23;
    asm("cvt.rn.bf16x2.f32 %0, %1, %2;" : "=r"(h01) : "f"(v.y), "f"(v.x));
    asm("cvt.rn.bf16x2.f32 %0, %1, %2;" : "=r"(h23) : "f"(v.w), "f"(v.z));
    float h0 = __uint_as_float(h01 << 16);
    float h1 = __uint_as_float(h01 & 0xFFFF0000u);
    float h2 = __uint_as_float(h23 << 16);
    float h3 = __uint_as_float(h23 & 0xFFFF0000u);
    uint32_t l01, l23;
    asm("cvt.rn.bf16x2.f32 %0, %1, %2;" : "=r"(l01) : "f"(v.y - h1), "f"(v.x - h0));
    asm("cvt.rn.bf16x2.f32 %0, %1, %2;" : "=r"(l23) : "f"(v.w - h3), "f"(v.z - h2));
    hp.x = h01; hp.y = h23;
    lp.x = l01; lp.y = l23;
}

// ---- prepass: 20 CTAs x 128 thr -> bf16 hi|lo smem image (parallel, ~1us) ----
__global__ void prep_A_kernel(const float* __restrict__ wq,
                              const float* __restrict__ wk,
                              const float* __restrict__ wv) {
    char* dst = (char*)g_Abuf;
    int f = blockIdx.x * 64 + (threadIdx.x & 63);   // 20*64 = 1280 items
    if ((threadIdx.x & 64) == 0) {
        int row = f >> 4, c4 = f & 15;
        const float* src = (row < 64) ? (wv + row * 64 + c4 * 4)
                         : (row < 72) ? (wq + (row - 64) * 64 + c4 * 4)
                                      : (wk + (row - 72) * 64 + c4 * 4);
        float4 v = *(const float4*)src;
        uint2 hp, lp;
        split_pack_fast(v, hp, lp);
        *(uint2*)(dst + row * APB + c4 * 8) = hp;
        *(uint2*)(dst + row * APB + 128 + c4 * 8) = lp;
    }
}

// One (m, nt-group) GEMM unit with compile-time NT so the j-loop fully unrolls.
template<int NT>
__device__ __forceinline__ void gemm_unit(
    const uint32_t sb, char* smem, int h, int m, int ntBeg, int lid)
{
    float* s_z  = (float*)(smem + OFF_Z);
    float* s_qT = (float*)(smem + OFF_QT);
    float* s_kT = (float*)(smem + OFF_KT);
    float* s_bq = (float*)(smem + OFF_BQ);
    float* s_bk = (float*)(smem + OFF_BK);

    float d[NT * 4];
#pragma unroll
    for (int i = 0; i < NT * 4; i++) d[i] = 0.f;

    const uint32_t aaddr = sb + OFF_A + (uint32_t)(lid & 15) * APB
                         + (uint32_t)(lid & 16) + (uint32_t)(16 * m) * APB;

#pragma unroll
    for (int ktp = 0; ktp < 2; ktp++) {
        uint32_t ah[8], al[8];
        ldsm4(ah,     aaddr + ktp * 64);
        ldsm4(ah + 4, aaddr + ktp * 64 + 32);
        ldsm4(al,     aaddr + 128 + ktp * 64);
        ldsm4(al + 4, aaddr + 128 + ktp * 64 + 32);
        uint32_t brow = sb + (uint32_t)(ktp * 32 + lid) * BPB;
#pragma unroll
        for (int j = 0; j < NT; j++) {
            int nt = ntBeg + j;
            uint32_t bh[4], bl[4];
            ldsm4t(bh, brow + OFF_BH + nt * 16);
            ldsm4t(bl, brow + OFF_BL + nt * 16);
            float* dj = d + 4 * j;
            mma16816(dj, ah,     bh);
            mma16816(dj, ah,     bl);
            mma16816(dj, al,     bh);
            mma16816(dj, ah + 4, bh + 2);
            mma16816(dj, ah + 4, bl + 2);
            mma16816(dj, al + 4, bh + 2);
        }
    }

    int r = lid >> 2;
#pragma unroll
    for (int j = 0; j < NT; j++) {
        int nt = ntBeg + j;
        int gp = h * 48 + nt * 8 + 2 * (lid & 3);
        float* dj = d + 4 * j;
        if (m < 4) {
            *(float2*)(s_z + (16 * m + r) * ZSP + gp)     = make_float2(dj[0], dj[1]);
            *(float2*)(s_z + (16 * m + r + 8) * ZSP + gp) = make_float2(dj[2], dj[3]);
        } else {
            float bqv = s_bq[r], bkv = s_bk[r];
            s_qT[gp * QKP + r]       = dj[0] + bqv;
            s_qT[(gp + 1) * QKP + r] = dj[1] + bqv;
            s_kT[gp * QKP + r]       = dj[2] + bkv;
            s_kT[(gp + 1) * QKP + r] = dj[3] + bkv;
        }
    }
}

__global__ __launch_bounds__(NTHREADS, 3)
void win_attn_kernel(const float* __restrict__ x,
                     const float* __restrict__ wq, const float* __restrict__ bq,
                     const float* __restrict__ wk, const float* __restrict__ bk,
                     const float* __restrict__ wv, const float* __restrict__ bv,
                     float* __restrict__ out) {
    extern __shared__ char smem[];
    const uint32_t sb = smem_u32(smem);
    float* s_z   = (float*)(smem + OFF_Z);
    float* s_qT  = (float*)(smem + OFF_QT);
    float* s_kT  = (float*)(smem + OFF_KT);
    float* s_att = (float*)(smem + OFF_ATT);
    float* s_bq  = (float*)(smem + OFF_BQ);
    float* s_bk  = (float*)(smem + OFF_BK);
    float* s_bv  = (float*)(smem + OFF_BV);
    float* obuf  = (float*)(smem + OFF_OBUF);

    const int tid = threadIdx.x;
    const int wid = tid >> 5;
    const int lid = tid & 31;

    const int b    = blockIdx.x / TILES_PER_B;
    const int tile = blockIdx.x % TILES_PER_B;
    const long n0  = (long)tile * TP;
    const float* xb = x   + (long)b * CCH * NVOX + n0;
    float*       ob = out + (long)b * CCH * NVOX + n0;

    // ---- A: straight copy of the pre-converted smem image (L2-hot) ----
    {
        uint4* dsta = (uint4*)(smem + OFF_A);
        for (int f = tid; f < A_BYTES / 16; f += NTHREADS)
            dsta[f] = g_Abuf[f];
    }
    // ---- biases ----
    if (tid < CO)                      s_bq[tid]       = bq[tid];
    if (tid >= 64 && tid < 64 + CO)    s_bk[tid - 64]  = bk[tid - 64];
    if (tid >= 128 && tid < 128 + CCH) s_bv[tid - 128] = bv[tid - 128];
    // ---- B half 0: x [ch][pos 0..55] bf16 hi/lo, pitch 112B ----
    for (int f = tid; f < CCH * 14; f += NTHREADS) {
        int ch = f / 14, p4 = f % 14;
        float4 v = *(const float4*)(xb + (long)ch * NVOX + p4 * 4);
        uint2 hp, lp;
        split_pack_fast(v, hp, lp);
        *(uint2*)(smem + OFF_BH + ch * BPB + p4 * 8) = hp;
        *(uint2*)(smem + OFF_BL + ch * BPB + p4 * 8) = lp;
    }
    __syncthreads();

    // ---- GEMM: D(80x104) = Ah Bh + Ah Bl + Al Bh, two 56-pos halves ----
    const int mA = wid >> 1;
    const int ng = wid & 1;

    for (int h = 0; h < 2; h++) {
        if (h == 1) {
            __syncthreads();   // everyone done reading B half 0
            for (int f = tid; f < CCH * 14; f += NTHREADS) {
                int ch = f / 14, p4 = f % 14;
                float4 v = *(const float4*)(xb + (long)ch * NVOX + 48 + p4 * 4);
                uint2 hp, lp;
                split_pack_fast(v, hp, lp);
                *(uint2*)(smem + OFF_BH + ch * BPB + p4 * 8) = hp;
                *(uint2*)(smem + OFF_BL + ch * BPB + p4 * 8) = lp;
            }
            __syncthreads();
        }
        if (wid == 0) {
            gemm_unit<4>(sb, smem, h, 0, 0, lid);
            gemm_unit<4>(sb, smem, h, 4, 0, lid);
        } else if (wid == 1) {
            gemm_unit<3>(sb, smem, h, 0, 4, lid);
            gemm_unit<3>(sb, smem, h, 4, 4, lid);
        } else if (ng == 0) {
            gemm_unit<4>(sb, smem, h, mA, 0, lid);
        } else {
            gemm_unit<3>(sb, smem, h, mA, 4, lid);
        }
    }
    __syncthreads();

    // ---- scores: 8 windows x 13x13, packed dot over 8 q/k channels ----
    for (int m = tid; m < WPB * WIN * WIN; m += NTHREADS) {
        int w  = m / (WIN * WIN);
        int ij = m % (WIN * WIN);
        int ii = ij / WIN, jj = ij % WIN;
        ulonglong2 qa = *(const ulonglong2*)&s_qT[(w * WIN + ii) * QKP];
        ulonglong2 qb = *(const ulonglong2*)&s_qT[(w * WIN + ii) * QKP + 4];
        ulonglong2 ka = *(const ulonglong2*)&s_kT[(w * WIN + jj) * QKP];
        ulonglong2 kb = *(const ulonglong2*)&s_kT[(w * WIN + jj) * QKP + 4];
        u64 acc = fma2(qa.x, ka.x,
                  fma2(qa.y, ka.y,
                  fma2(qb.x, kb.x,
                  mul2(qb.y, kb.y))));
        s_att[w * AWS + ii * ARP + jj] = lo2(acc) + hi2(acc);
    }
    __syncthreads();

    // ---- softmax over 104 rows of length 13 ----
    if (tid < TP) {
        int w = tid / WIN, ii = tid % WIN;
        float* row = &s_att[w * AWS + ii * ARP];
        float4 ra = *(const float4*)row;
        float4 rb = *(const float4*)(row + 4);
        float4 rc = *(const float4*)(row + 8);
        float  rd = row[12];
        float m0 = fmaxf(fmaxf(fmaxf(ra.x, ra.y), fmaxf(ra.z, ra.w)),
                   fmaxf(fmaxf(fmaxf(rb.x, rb.y), fmaxf(rb.z, rb.w)),
                   fmaxf(fmaxf(fmaxf(rc.x, rc.y), fmaxf(rc.z, rc.w)), rd)));
        ra.x = __expf(ra.x - m0); ra.y = __expf(ra.y - m0);
        ra.z = __expf(ra.z - m0); ra.w = __expf(ra.w - m0);
        rb.x = __expf(rb.x - m0); rb.y = __expf(rb.y - m0);
        rb.z = __expf(rb.z - m0); rb.w = __expf(rb.w - m0);
        rc.x = __expf(rc.x - m0); rc.y = __expf(rc.y - m0);
        rc.z = __expf(rc.z - m0); rc.w = __expf(rc.w - m0);
        rd   = __expf(rd   - m0);
        float sum = ra.x + ra.y + ra.z + ra.w + rb.x + rb.y + rb.z + rb.w
                  + rc.x + rc.y + rc.z + rc.w + rd;
        float inv = __frcp_rn(sum);
        ra.x *= inv; ra.y *= inv; ra.z *= inv; ra.w *= inv;
        rb.x *= inv; rb.y *= inv; rb.z *= inv; rb.w *= inv;
        rc.x *= inv; rc.y *= inv; rc.z *= inv; rc.w *= inv;
        rd   *= inv;
        *(float4*)row       = ra;
        *(float4*)(row + 4) = rb;
        *(float4*)(row + 8) = rc;
        row[12] = rd;
    }
    __syncthreads();

    // ---- att-apply: out = z . att^T + bv (z/att from smem), staged to obuf ----
    {
        const int ct = tid >> 3;       // 0..31 channel pair
        const int pt = tid & 7;        // 0..7  window
        const int c0 = ct * 2;

        const float* zr0 = s_z + c0 * ZSP + pt * WIN;
        const float* zr1 = zr0 + ZSP;
        float z0[WIN], z1[WIN];
#pragma unroll
        for (int j = 0; j < WIN; j++) { z0[j] = zr0[j]; z1[j] = zr1[j]; }

        u64 zp0[6], zp1[6];
#pragma unroll
        for (int q = 0; q < 6; q++) {
            zp0[q] = pack2(z0[2*q], z0[2*q + 1]);
            zp1[q] = pack2(z1[2*q], z1[2*q + 1]);
        }
        const float z0s = z0[12], z1s = z1[12];

        const float* ar = &s_att[pt * AWS];
        const float bv0 = s_bv[c0], bv1 = s_bv[c0 + 1];
        float* ob0 = obuf + c0 * OBP + pt * WIN;
        float* ob1 = ob0 + OBP;
#pragma unroll
        for (int i = 0; i < WIN; i++) {
            const float* ari = ar + i * ARP;
            ulonglong2 aA = *(const ulonglong2*)ari;
            ulonglong2 aB = *(const ulonglong2*)(ari + 4);
            ulonglong2 aC = *(const ulonglong2*)(ari + 8);
            float a12 = ari[12];
            u64 s0 = fma2(zp0[0], aA.x,
                     fma2(zp0[1], aA.y,
                     fma2(zp0[2], aB.x,
                     fma2(zp0[3], aB.y,
                     fma2(zp0[4], aC.x,
                     mul2(zp0[5], aC.y))))));
            u64 s1 = fma2(zp1[0], aA.x,
                     fma2(zp1[1], aA.y,
                     fma2(zp1[2], aB.x,
                     fma2(zp1[3], aB.y,
                     fma2(zp1[4], aC.x,
                     mul2(zp1[5], aC.y))))));
            ob0[i] = lo2(s0) + hi2(s0) + fmaf(z0s, a12, bv0);
            ob1[i] = lo2(s1) + hi2(s1) + fmaf(z1s, a12, bv1);
        }
    }
    __syncthreads();

    // ---- coalesced global store: 64 rows x 104 floats as float4 ----
    for (int i = tid; i < CCH * (TP / 4); i += NTHREADS) {
        int r  = i / (TP / 4);
        int c4 = i % (TP / 4);
        float4 v = *reinterpret_cast<const float4*>(obuf + r * OBP + c4 * 4);
        *reinterpret_cast<float4*>(ob + (long)r * NVOX + c4 * 4) = v;
    }
}

extern "C" void kernel_launch(void* const* d_in, const int* in_sizes, int n_in,
                              void* d_out, int out_size) {
    const float* x  = (const float*)d_in[0];
    const float* wq = (const float*)d_in[1];
    const float* bq = (const float*)d_in[2];
    const float* wk = (const float*)d_in[3];
    const float* bk = (const float*)d_in[4];
    const float* wv = (const float*)d_in[5];
    const float* bv = (const float*)d_in[6];
    float* out = (float*)d_out;

    const int B = in_sizes[0] / (CCH * NVOX);   // 8

    static bool attr_set = false;
    if (!attr_set) {
        cudaFuncSetAttribute(win_attn_kernel,
                             cudaFuncAttributeMaxDynamicSharedMemorySize, SMEM_BYTES);
        attr_set = true;
    }

    prep_A_kernel<<<20, 128>>>(wq, wk, wv);
    dim3 grid(B * TILES_PER_B);
    win_attn_kernel<<<grid, NTHREADS, SMEM_BYTES>>>(x, wq, bq, wk, bk, wv, bv, out);
}